// round 14
// baseline (speedup 1.0000x reference)
#include <cuda_runtime.h>
#include <cuda_bf16.h>
#include <cstdint>

#define NN   100000
#define EE   600000
#define HH   128
#define CC   47
#define LL   3
#define EPSV 1e-5f

#define ASTR 136
#define BSTR 264
#define APLANE (128 * ASTR * 2)   // 34816 B
#define BPLANE (128 * BSTR * 2)   // 67584 B
#define NTILE ((NN + 127) / 128)  // 782

#define OROWS 256
#define OAPLANE (OROWS * ASTR * 2)  // 69632 B
#define OBPLANE (48 * ASTR * 2)     // 13056 B
#define ONTILE ((NN + OROWS - 1) / OROWS)  // 391

#define SBS  512
#define SNB  ((NN + SBS - 1) / SBS)   // 196

// Scratch (device globals; no allocation allowed)
__device__ float g_h[NN * HH];
__device__ float g_agg[NN * HH];
__device__ unsigned short g_wbhi_in[128 * ASTR];
__device__ unsigned short g_wblo_in[128 * ASTR];
__device__ unsigned short g_wbhi_l[LL * 128 * BSTR];
__device__ unsigned short g_wblo_l[LL * 128 * BSTR];
__device__ unsigned short g_wbhi_o[48 * ASTR];
__device__ unsigned short g_wblo_o[48 * ASTR];
__device__ int   g_ideg[NN];
__device__ int   g_rs[NN + 1];
__device__ int   g_bsum[SNB];
__device__ int   g_boff[SNB];
__device__ int   g_cursor[NN];
__device__ int   g_csrc[EE];

// ---------------------------------------------------------------------------
__device__ __forceinline__ uint32_t smem_u32(const void* p) {
    uint32_t a;
    asm("{ .reg .u64 t; cvta.to.shared.u64 t, %1; cvt.u32.u64 %0, t; }"
        : "=r"(a) : "l"(p));
    return a;
}
__device__ __forceinline__ void ldsm4(uint32_t* r, uint32_t addr) {
    asm volatile("ldmatrix.sync.aligned.m8n8.x4.shared.b16 {%0,%1,%2,%3}, [%4];"
                 : "=r"(r[0]), "=r"(r[1]), "=r"(r[2]), "=r"(r[3]) : "r"(addr));
}
__device__ __forceinline__ void mma16816(float* c, const uint32_t* a, const uint32_t* b) {
    asm volatile(
        "mma.sync.aligned.m16n8k16.row.col.f32.bf16.bf16.f32 "
        "{%0,%1,%2,%3}, {%4,%5,%6,%7}, {%8,%9}, {%0,%1,%2,%3};"
        : "+f"(c[0]), "+f"(c[1]), "+f"(c[2]), "+f"(c[3])
        : "r"(a[0]), "r"(a[1]), "r"(a[2]), "r"(a[3]), "r"(b[0]), "r"(b[1]));
}
__device__ __forceinline__ void split1(float x, unsigned short& hi, unsigned short& lo) {
    __nv_bfloat16 h = __float2bfloat16(x);
    float r = x - __bfloat162float(h);
    __nv_bfloat16 l = __float2bfloat16(r);
    hi = __bfloat16_as_ushort(h);
    lo = __bfloat16_as_ushort(l);
}
__device__ __forceinline__ float tof(unsigned short hi, unsigned short lo) {
    return __uint_as_float((uint32_t)hi << 16) + __uint_as_float((uint32_t)lo << 16);
}
__device__ __forceinline__ void cpa16(uint32_t dst, const void* src) {
    asm volatile("cp.async.cg.shared.global [%0], [%1], 16;" :: "r"(dst), "l"(src));
}
#define CP_COMMIT() asm volatile("cp.async.commit_group;" ::: "memory")
#define CP_WAIT0()  asm volatile("cp.async.wait_group 0;" ::: "memory")

// ---------------------------------------------------------------------------
// weight prep
__global__ void k_prep_in(const float* __restrict__ W) {
    int i = blockIdx.x * blockDim.x + threadIdx.x;
    if (i >= 128 * ASTR) return;
    int n = i / ASTR, k = i - n * ASTR;
    unsigned short hi = 0, lo = 0;
    if (k < 128) split1(W[k * 128 + n], hi, lo);
    g_wbhi_in[i] = hi;
    g_wblo_in[i] = lo;
}

__global__ void k_prep_layer(const float* __restrict__ Wl, const float* __restrict__ Wr) {
    int l = blockIdx.y;
    int i = blockIdx.x * blockDim.x + threadIdx.x;
    if (i >= 128 * BSTR) return;
    int n = i / BSTR, k = i - n * BSTR;
    unsigned short hi = 0, lo = 0;
    if (k < 128) split1(Wl[(long long)l * HH * HH + k * 128 + n], hi, lo);
    else if (k < 256) split1(Wr[(long long)l * HH * HH + (k - 128) * 128 + n], hi, lo);
    long long o = (long long)l * 128 * BSTR + i;
    g_wbhi_l[o] = hi;
    g_wblo_l[o] = lo;
}

__global__ void k_prep_out(const float* __restrict__ W) {
    int i = blockIdx.x * blockDim.x + threadIdx.x;
    if (i >= 48 * ASTR) return;
    int n = i / ASTR, k = i - n * ASTR;
    unsigned short hi = 0, lo = 0;
    if (k < 128 && n < CC) split1(W[k * CC + n], hi, lo);
    g_wbhi_o[i] = hi;
    g_wblo_o[i] = lo;
}

// ---------------------------------------------------------------------------
// CSR build
__global__ void k_zero2(int* __restrict__ a, int* __restrict__ b, int n) {
    int i = blockIdx.x * blockDim.x + threadIdx.x;
    if (i < n) { a[i] = 0; b[i] = 0; }
}

__global__ void k_hist(const int* __restrict__ dst) {
    int e = blockIdx.x * blockDim.x + threadIdx.x;
    if (e < EE) atomicAdd(&g_ideg[dst[e]], 1);
}

__global__ void __launch_bounds__(SBS) k_blocksum() {
    __shared__ int s[SBS];
    int i = blockIdx.x * SBS + threadIdx.x;
    s[threadIdx.x] = (i < NN) ? g_ideg[i] : 0;
    __syncthreads();
    for (int off = SBS / 2; off > 0; off >>= 1) {
        if (threadIdx.x < off) s[threadIdx.x] += s[threadIdx.x + off];
        __syncthreads();
    }
    if (threadIdx.x == 0) g_bsum[blockIdx.x] = s[0];
}

__global__ void __launch_bounds__(256) k_scanb() {
    __shared__ int s[SNB];
    int t = threadIdx.x;
    if (t < SNB) s[t] = g_bsum[t];
    __syncthreads();
    if (t == 0) {
        int acc = 0;
        for (int b = 0; b < SNB; b++) { int v = s[b]; s[b] = acc; acc += v; }
        g_rs[NN] = EE;
    }
    __syncthreads();
    if (t < SNB) g_boff[t] = s[t];
}

__global__ void __launch_bounds__(SBS) k_localscan() {
    __shared__ int s[SBS];
    int i = blockIdx.x * SBS + threadIdx.x;
    int d = (i < NN) ? g_ideg[i] : 0;
    s[threadIdx.x] = d;
    __syncthreads();
    for (int off = 1; off < SBS; off <<= 1) {
        int t = (threadIdx.x >= off) ? s[threadIdx.x - off] : 0;
        __syncthreads();
        s[threadIdx.x] += t;
        __syncthreads();
    }
    if (i < NN) g_rs[i] = g_boff[blockIdx.x] + s[threadIdx.x] - d;
}

__global__ void k_fill(const int* __restrict__ src, const int* __restrict__ dst) {
    int e = blockIdx.x * blockDim.x + threadIdx.x;
    if (e >= EE) return;
    int d = dst[e];
    int pos = g_rs[d] + atomicAdd(&g_cursor[d], 1);
    g_csrc[pos] = src[e];
}

// ---------------------------------------------------------------------------
// gather mean: agg[n] = mean of h[src] over in-edges (one warp per node)
__global__ void __launch_bounds__(256) k_gather() {
    int w = (blockIdx.x * blockDim.x + threadIdx.x) >> 5;
    int lane = threadIdx.x & 31;
    if (w >= NN) return;
    int beg = g_rs[w], end = g_rs[w + 1];
    const float4* h4 = (const float4*)g_h;
    float4 acc = make_float4(0.f, 0.f, 0.f, 0.f);
    int j = beg;
    for (; j + 1 < end; j += 2) {
        int s0 = g_csrc[j], s1 = g_csrc[j + 1];
        float4 v0 = __ldg(&h4[(long long)s0 * 32 + lane]);
        float4 v1 = __ldg(&h4[(long long)s1 * 32 + lane]);
        acc.x += v0.x + v1.x; acc.y += v0.y + v1.y;
        acc.z += v0.z + v1.z; acc.w += v0.w + v1.w;
    }
    if (j < end) {
        int s0 = g_csrc[j];
        float4 v0 = __ldg(&h4[(long long)s0 * 32 + lane]);
        acc.x += v0.x; acc.y += v0.y; acc.z += v0.z; acc.w += v0.w;
    }
    float inv = 1.0f / (float)max(end - beg, 1);
    acc.x *= inv; acc.y *= inv; acc.z *= inv; acc.w *= inv;
    ((float4*)g_agg)[(long long)w * 32 + lane] = acc;
}

// ---------------------------------------------------------------------------
// helpers: MLP=8 tile load + convert to split planes
__device__ __forceinline__ void load_tile8(float4* v, const float4* srcp, int row0, int tid) {
#pragma unroll
    for (int u = 0; u < 8; u++) {
        int i = tid + u * 512;
        int r = i >> 5, c4 = i & 31;
        int gr = row0 + r;
        v[u] = (gr < NN) ? __ldg(&srcp[(long long)gr * 32 + c4])
                         : make_float4(0.f, 0.f, 0.f, 0.f);
    }
}
__device__ __forceinline__ void conv_tile8(const float4* v, unsigned short* Ahi,
                                           unsigned short* Alo, int tid) {
#pragma unroll
    for (int u = 0; u < 8; u++) {
        int i = tid + u * 512;
        int r = i >> 5, k = (i & 31) * 4;
        ushort4 UH, UL;
        split1(v[u].x, UH.x, UL.x); split1(v[u].y, UH.y, UL.y);
        split1(v[u].z, UH.z, UL.z); split1(v[u].w, UH.w, UL.w);
        *(ushort4*)&Ahi[r * ASTR + k] = UH;
        *(ushort4*)&Alo[r * ASTR + k] = UL;
    }
}

// Load one k-step's fragments into buffer `buf` at chunk-local offset kk
#define LOAD_FRAGS(buf, kk)                                                      \
    {                                                                            \
        _Pragma("unroll")                                                        \
        for (int mt = 0; mt < 2; mt++) {                                         \
            uint32_t off = (wm * 32 + mt * 16 + a_row) * (ASTR * 2) +            \
                           ((kk) + a_koff) * 2;                                  \
            ldsm4(fah[buf][mt], sAhi_ + off);                                    \
            ldsm4(fal[buf][mt], sAlo_ + off);                                    \
        }                                                                        \
        _Pragma("unroll")                                                        \
        for (int g = 0; g < 2; g++) {                                            \
            uint32_t off = (wn * 32 + g * 16 + b_row) * (bstr_ * 2) +            \
                           (kb_ + (kk) + b_koff) * 2;                            \
            uint32_t tt[4];                                                      \
            ldsm4(tt, sBhi_ + off);                                              \
            fbh[buf][2 * g][0] = tt[0]; fbh[buf][2 * g][1] = tt[1];              \
            fbh[buf][2 * g + 1][0] = tt[2]; fbh[buf][2 * g + 1][1] = tt[3];      \
            ldsm4(tt, sBlo_ + off);                                              \
            fbl[buf][2 * g][0] = tt[0]; fbl[buf][2 * g][1] = tt[1];              \
            fbl[buf][2 * g + 1][0] = tt[2]; fbl[buf][2 * g + 1][1] = tt[3];      \
        }                                                                        \
    }

// Software-pipelined MMA over one 128-k chunk (4x4 warp tiling, 32x32 warp tile)
#define MMA_CHUNK(cacc, sAhi, sAlo, sBhi, sBlo, bstr, kb)                        \
    do {                                                                         \
        uint32_t sAhi_ = (sAhi), sAlo_ = (sAlo), sBhi_ = (sBhi), sBlo_ = (sBlo); \
        const int bstr_ = (bstr), kb_ = (kb);                                    \
        uint32_t fah[2][2][4], fal[2][2][4];                                     \
        uint32_t fbh[2][4][2], fbl[2][4][2];                                     \
        LOAD_FRAGS(0, 0)                                                         \
        _Pragma("unroll")                                                        \
        for (int ks = 0; ks < 8; ks++) {                                         \
            int cur = ks & 1;                                                    \
            if (ks < 7) LOAD_FRAGS(cur ^ 1, (ks + 1) * 16)                       \
            _Pragma("unroll")                                                    \
            for (int mt = 0; mt < 2; mt++)                                       \
                _Pragma("unroll")                                                \
                for (int nt = 0; nt < 4; nt++) {                                 \
                    mma16816(cacc[mt][nt], fah[cur][mt], fbh[cur][nt]);          \
                    mma16816(cacc[mt][nt], fah[cur][mt], fbl[cur][nt]);          \
                    mma16816(cacc[mt][nt], fal[cur][mt], fbh[cur][nt]);          \
                }                                                                \
        }                                                                        \
    } while (0)

// ---------------------------------------------------------------------------
// input GEMM (mma.sync bf16 3-term split), PERSISTENT: h = relu(bn(x@W+b))
extern "C" __global__ void __launch_bounds__(512)
k_in_mma(const float* __restrict__ x, const float* __restrict__ bias,
         const float* __restrict__ bng, const float* __restrict__ bnb,
         const float* __restrict__ bnm, const float* __restrict__ bnv) {
    extern __shared__ char sm[];
    float* scp = (float*)sm;
    float* shp = (float*)(sm + 512);
    const uint32_t OFF_AHI = 1024;
    const uint32_t OFF_ALO = OFF_AHI + APLANE;
    const uint32_t OFF_BHI = OFF_ALO + APLANE;
    const uint32_t OFF_BLO = OFF_BHI + APLANE;
    unsigned short* Ahi = (unsigned short*)(sm + OFF_AHI);
    unsigned short* Alo = (unsigned short*)(sm + OFF_ALO);
    int tid = threadIdx.x;
    int wid = tid >> 5, lane = tid & 31;
    uint32_t sbase = smem_u32(sm);

    {
        const char* bh = (const char*)g_wbhi_in;
        const char* bl = (const char*)g_wblo_in;
        for (int i = tid * 16; i < APLANE; i += 512 * 16) {
            cpa16(sbase + OFF_BHI + i, bh + i);
            cpa16(sbase + OFF_BLO + i, bl + i);
        }
        CP_COMMIT();
    }
    if (tid < 128) {
        int c = tid;
        float s = bng[c] * rsqrtf(bnv[c] + EPSV);
        scp[c] = s;
        shp[c] = bnb[c] - bnm[c] * s + bias[c] * s;
    }
    CP_WAIT0();
    __syncthreads();

    int wm = wid & 3, wn = wid >> 2;   // 4x4 warp grid, warp tile 32x32
    uint32_t sAhi = sbase + OFF_AHI, sAlo = sbase + OFF_ALO;
    uint32_t sBhi = sbase + OFF_BHI, sBlo = sbase + OFF_BLO;
    uint32_t a_row = (lane & 15);
    uint32_t a_koff = (lane >> 4) << 3;
    uint32_t b_row = ((lane >> 4) << 3) + (lane & 7);
    uint32_t b_koff = ((lane >> 3) & 1) << 3;
    const float4* x4 = (const float4*)x;
    float2* h2 = (float2*)g_h;
    int rq = lane >> 2, cp = (lane & 3) * 2;

    for (int t = blockIdx.x; t < NTILE; t += gridDim.x) {
        int row0 = t * 128;
        {
            float4 v[8];
            load_tile8(v, x4, row0, tid);
            conv_tile8(v, Ahi, Alo, tid);
        }
        __syncthreads();

        float c[2][4][4];
#pragma unroll
        for (int mt = 0; mt < 2; mt++)
#pragma unroll
            for (int nt = 0; nt < 4; nt++)
#pragma unroll
                for (int q = 0; q < 4; q++) c[mt][nt][q] = 0.f;

        MMA_CHUNK(c, sAhi, sAlo, sBhi, sBlo, ASTR, 0);

#pragma unroll
        for (int mt = 0; mt < 2; mt++)
#pragma unroll
            for (int nt = 0; nt < 4; nt++) {
                int col = wn * 32 + nt * 8 + cp;
                float s0 = scp[col], s1 = scp[col + 1];
                float t0 = shp[col], t1 = shp[col + 1];
                int r0g = row0 + wm * 32 + mt * 16 + rq;
                if (r0g < NN) {
                    float2 o;
                    o.x = fmaxf(fmaf(c[mt][nt][0], s0, t0), 0.f);
                    o.y = fmaxf(fmaf(c[mt][nt][1], s1, t1), 0.f);
                    h2[(long long)r0g * 64 + (col >> 1)] = o;
                }
                int r1g = r0g + 8;
                if (r1g < NN) {
                    float2 o;
                    o.x = fmaxf(fmaf(c[mt][nt][2], s0, t0), 0.f);
                    o.y = fmaxf(fmaf(c[mt][nt][3], s1, t1), 0.f);
                    h2[(long long)r1g * 64 + (col >> 1)] = o;
                }
            }
        __syncthreads();
    }
}

// ---------------------------------------------------------------------------
// layer GEMM, PERSISTENT: t = relu(bn([agg|h] @ [Wl;Wr] + bl)); h += t
extern "C" __global__ void __launch_bounds__(512)
k_layer_mma(int l, const float* __restrict__ blv,
            const float* __restrict__ bng, const float* __restrict__ bnb,
            const float* __restrict__ bnm, const float* __restrict__ bnv) {
    extern __shared__ char sm[];
    float* scp = (float*)sm;
    float* shp = (float*)(sm + 512);
    const uint32_t OFF_AHI = 1024;
    const uint32_t OFF_ALO = OFF_AHI + APLANE;
    const uint32_t OFF_BHI = OFF_ALO + APLANE;
    const uint32_t OFF_BLO = OFF_BHI + BPLANE;
    unsigned short* Ahi = (unsigned short*)(sm + OFF_AHI);
    unsigned short* Alo = (unsigned short*)(sm + OFF_ALO);
    int tid = threadIdx.x;
    int wid = tid >> 5, lane = tid & 31;
    uint32_t sbase = smem_u32(sm);

    {
        const char* bh = (const char*)(g_wbhi_l + (long long)l * 128 * BSTR);
        const char* bl = (const char*)(g_wblo_l + (long long)l * 128 * BSTR);
        for (int i = tid * 16; i < BPLANE; i += 512 * 16) {
            cpa16(sbase + OFF_BHI + i, bh + i);
            cpa16(sbase + OFF_BLO + i, bl + i);
        }
        CP_COMMIT();
    }
    if (tid < 128) {
        int c = tid;
        float s = bng[l * HH + c] * rsqrtf(bnv[l * HH + c] + EPSV);
        scp[c] = s;
        shp[c] = bnb[l * HH + c] - bnm[l * HH + c] * s + blv[l * HH + c] * s;
    }
    CP_WAIT0();
    __syncthreads();

    int wm = wid & 3, wn = wid >> 2;
    uint32_t sAhi = sbase + OFF_AHI, sAlo = sbase + OFF_ALO;
    uint32_t sBhi = sbase + OFF_BHI, sBlo = sbase + OFF_BLO;
    uint32_t a_row = (lane & 15);
    uint32_t a_koff = (lane >> 4) << 3;
    uint32_t b_row = ((lane >> 4) << 3) + (lane & 7);
    uint32_t b_koff = ((lane >> 3) & 1) << 3;
    const float4* agg4 = (const float4*)g_agg;
    const float4* h4g = (const float4*)g_h;
    float2* h2 = (float2*)g_h;
    int rq = lane >> 2, cp = (lane & 3) * 2;

    for (int t = blockIdx.x; t < NTILE; t += gridDim.x) {
        int row0 = t * 128;
        float c[2][4][4];
#pragma unroll
        for (int mt = 0; mt < 2; mt++)
#pragma unroll
            for (int nt = 0; nt < 4; nt++)
#pragma unroll
                for (int q = 0; q < 4; q++) c[mt][nt][q] = 0.f;

        // chunk0: A = agg
        {
            float4 v[8];
            load_tile8(v, agg4, row0, tid);
            conv_tile8(v, Ahi, Alo, tid);
        }
        __syncthreads();
        MMA_CHUNK(c, sAhi, sAlo, sBhi, sBlo, BSTR, 0);
        __syncthreads();

        // chunk1: A = h
        {
            float4 v[8];
            load_tile8(v, h4g, row0, tid);
            conv_tile8(v, Ahi, Alo, tid);
        }
        __syncthreads();
        MMA_CHUNK(c, sAhi, sAlo, sBhi, sBlo, BSTR, 128);

        // epilogue: residual h reconstructed from chunk1 smem planes
#pragma unroll
        for (int mt = 0; mt < 2; mt++)
#pragma unroll
            for (int nt = 0; nt < 4; nt++) {
                int col = wn * 32 + nt * 8 + cp;
                float s0 = scp[col], s1 = scp[col + 1];
                float t0 = shp[col], t1 = shp[col + 1];
                int r0 = wm * 32 + mt * 16 + rq;
                int r0g = row0 + r0;
                if (r0g < NN) {
                    float hx = tof(Ahi[r0 * ASTR + col], Alo[r0 * ASTR + col]);
                    float hy = tof(Ahi[r0 * ASTR + col + 1], Alo[r0 * ASTR + col + 1]);
                    float2 o;
                    o.x = hx + fmaxf(fmaf(c[mt][nt][0], s0, t0), 0.f);
                    o.y = hy + fmaxf(fmaf(c[mt][nt][1], s1, t1), 0.f);
                    h2[(long long)r0g * 64 + (col >> 1)] = o;
                }
                int r1 = r0 + 8;
                int r1g = row0 + r1;
                if (r1g < NN) {
                    float hx = tof(Ahi[r1 * ASTR + col], Alo[r1 * ASTR + col]);
                    float hy = tof(Ahi[r1 * ASTR + col + 1], Alo[r1 * ASTR + col + 1]);
                    float2 o;
                    o.x = hx + fmaxf(fmaf(c[mt][nt][2], s0, t0), 0.f);
                    o.y = hy + fmaxf(fmaf(c[mt][nt][3], s1, t1), 0.f);
                    h2[(long long)r1g * 64 + (col >> 1)] = o;
                }
            }
        __syncthreads();  // smem reads done before next tile's convert
    }
}

// ---------------------------------------------------------------------------
// output GEMM (mma.sync bf16 3-term split), PERSISTENT
extern "C" __global__ void __launch_bounds__(512)
k_out_mma(const float* __restrict__ bias, float* __restrict__ out) {
    extern __shared__ char sm[];
    float* bsp = (float*)sm;  // bias[48]
    const uint32_t OFF_AHI = 1024;
    const uint32_t OFF_ALO = OFF_AHI + OAPLANE;
    const uint32_t OFF_BHI = OFF_ALO + OAPLANE;
    const uint32_t OFF_BLO = OFF_BHI + OBPLANE;
    unsigned short* Ahi = (unsigned short*)(sm + OFF_AHI);
    unsigned short* Alo = (unsigned short*)(sm + OFF_ALO);
    int tid = threadIdx.x;
    int wid = tid >> 5, lane = tid & 31;
    uint32_t sbase = smem_u32(sm);

    {
        const char* bh = (const char*)g_wbhi_o;
        const char* bl = (const char*)g_wblo_o;
        for (int i = tid * 16; i < OBPLANE; i += 512 * 16) {
            cpa16(sbase + OFF_BHI + i, bh + i);
            cpa16(sbase + OFF_BLO + i, bl + i);
        }
        CP_COMMIT();
    }
    if (tid < 48) bsp[tid] = (tid < CC) ? bias[tid] : 0.f;
    CP_WAIT0();
    __syncthreads();

    int mwarp = wid * 16;
    uint32_t sAhi = sbase + OFF_AHI, sAlo = sbase + OFF_ALO;
    uint32_t sBhi = sbase + OFF_BHI, sBlo = sbase + OFF_BLO;
    uint32_t a_row = (lane & 15);
    uint32_t a_koff = (lane >> 4) << 3;
    uint32_t b_row = ((lane >> 4) << 3) + (lane & 7);
    uint32_t b_koff = ((lane >> 3) & 1) << 3;
    const float4* h4g = (const float4*)g_h;
    int rq = lane >> 2, cp = (lane & 3) * 2;

    for (int t = blockIdx.x; t < ONTILE; t += gridDim.x) {
        int row0 = t * OROWS;
        {
            float4 v[16];
#pragma unroll
            for (int u = 0; u < 16; u++) {
                int i = tid + u * 512;
                int r = i >> 5, c4 = i & 31;
                int gr = row0 + r;
                v[u] = (gr < NN) ? __ldg(&h4g[(long long)gr * 32 + c4])
                                 : make_float4(0.f, 0.f, 0.f, 0.f);
            }
#pragma unroll
            for (int u = 0; u < 16; u++) {
                int i = tid + u * 512;
                int r = i >> 5, k = (i & 31) * 4;
                ushort4 UH, UL;
                split1(v[u].x, UH.x, UL.x); split1(v[u].y, UH.y, UL.y);
                split1(v[u].z, UH.z, UL.z); split1(v[u].w, UH.w, UL.w);
                *(ushort4*)&Ahi[r * ASTR + k] = UH;
                *(ushort4*)&Alo[r * ASTR + k] = UL;
            }
        }
        __syncthreads();

        float c[6][4];
#pragma unroll
        for (int nt = 0; nt < 6; nt++)
#pragma unroll
            for (int q = 0; q < 4; q++) c[nt][q] = 0.f;

#pragma unroll 1
        for (int k0 = 0; k0 < 128; k0 += 16) {
            uint32_t ah[4], al[4];
            {
                uint32_t off = (mwarp + a_row) * (ASTR * 2) + (k0 + a_koff) * 2;
                ldsm4(ah, sAhi + off);
                ldsm4(al, sAlo + off);
            }
            uint32_t bh[6][2], bl[6][2];
#pragma unroll
            for (int g = 0; g < 3; g++) {
                uint32_t off = (g * 16 + b_row) * (ASTR * 2) + (k0 + b_koff) * 2;
                uint32_t tt[4];
                ldsm4(tt, sBhi + off);
                bh[2 * g][0] = tt[0]; bh[2 * g][1] = tt[1];
                bh[2 * g + 1][0] = tt[2]; bh[2 * g + 1][1] = tt[3];
                ldsm4(tt, sBlo + off);
                bl[2 * g][0] = tt[0]; bl[2 * g][1] = tt[1];
                bl[2 * g + 1][0] = tt[2]; bl[2 * g + 1][1] = tt[3];
            }
#pragma unroll
            for (int nt = 0; nt < 6; nt++) {
                mma16816(c[nt], ah, bh[nt]);
                mma16816(c[nt], ah, bl[nt]);
                mma16816(c[nt], al, bh[nt]);
            }
        }

#pragma unroll
        for (int nt = 0; nt < 6; nt++) {
            int col = nt * 8 + cp;
            float b0 = bsp[col], b1 = bsp[col + 1];
            int r0g = row0 + mwarp + rq;
            if (r0g < NN) {
                out[(long long)r0g * CC + col] = c[nt][0] + b0;
                if (col + 1 < CC) out[(long long)r0g * CC + col + 1] = c[nt][1] + b1;
            }
            int r1g = r0g + 8;
            if (r1g < NN) {
                out[(long long)r1g * CC + col] = c[nt][2] + b0;
                if (col + 1 < CC) out[(long long)r1g * CC + col + 1] = c[nt][3] + b1;
            }
        }
        __syncthreads();
    }
}

// ---------------------------------------------------------------------------
extern "C" void kernel_launch(void* const* d_in, const int* in_sizes, int n_in,
                              void* d_out, int out_size) {
    const float* x     = (const float*)d_in[0];
    const float* in_W  = (const float*)d_in[1];
    const float* in_b  = (const float*)d_in[2];
    const float* ibn_g = (const float*)d_in[3];
    const float* ibn_b = (const float*)d_in[4];
    const float* ibn_m = (const float*)d_in[5];
    const float* ibn_v = (const float*)d_in[6];
    const float* Wl    = (const float*)d_in[7];
    const float* bl    = (const float*)d_in[8];
    const float* Wr    = (const float*)d_in[9];
    const float* bn_g  = (const float*)d_in[10];
    const float* bn_b  = (const float*)d_in[11];
    const float* bn_m  = (const float*)d_in[12];
    const float* bn_v  = (const float*)d_in[13];
    const float* out_W = (const float*)d_in[14];
    const float* out_b = (const float*)d_in[15];
    const int*   ei    = (const int*)d_in[16];
    const int* src = ei;
    const int* dst = ei + EE;
    float* out = (float*)d_out;

    static bool attr_done = false;
    static int nsm = 148;
    static cudaStream_t sA = 0, sB = 0;
    static cudaEvent_t evFork = 0, evA = 0, evB = 0;
    size_t smem_in    = 1024 + 4ull * APLANE;                  // ~137 KB
    size_t smem_layer = 1024 + 2ull * APLANE + 2ull * BPLANE;  // ~201 KB
    size_t smem_out   = 1024 + 2ull * OAPLANE + 2ull * OBPLANE; // ~163 KB
    if (!attr_done) {
        cudaFuncSetAttribute(k_in_mma, cudaFuncAttributeMaxDynamicSharedMemorySize, (int)smem_in);
        cudaFuncSetAttribute(k_layer_mma, cudaFuncAttributeMaxDynamicSharedMemorySize, (int)smem_layer);
        cudaFuncSetAttribute(k_out_mma, cudaFuncAttributeMaxDynamicSharedMemorySize, (int)smem_out);
        cudaDeviceGetAttribute(&nsm, cudaDevAttrMultiProcessorCount, 0);
        cudaStreamCreateWithFlags(&sA, cudaStreamNonBlocking);
        cudaStreamCreateWithFlags(&sB, cudaStreamNonBlocking);
        cudaEventCreateWithFlags(&evFork, cudaEventDisableTiming);
        cudaEventCreateWithFlags(&evA, cudaEventDisableTiming);
        cudaEventCreateWithFlags(&evB, cudaEventDisableTiming);
        attr_done = true;
    }

    int* d_ideg;   cudaGetSymbolAddress((void**)&d_ideg, g_ideg);
    int* d_cursor; cudaGetSymbolAddress((void**)&d_cursor, g_cursor);

    // fork: stream A = weight prep + input GEMM; stream B = CSR build
    cudaEventRecord(evFork, 0);
    cudaStreamWaitEvent(sA, evFork, 0);
    cudaStreamWaitEvent(sB, evFork, 0);

    // stream A
    k_prep_in<<<(128 * ASTR + 255) / 256, 256, 0, sA>>>(in_W);
    k_prep_layer<<<dim3((128 * BSTR + 255) / 256, LL), 256, 0, sA>>>(Wl, Wr);
    k_prep_out<<<(48 * ASTR + 255) / 256, 256, 0, sA>>>(out_W);
    k_in_mma<<<nsm, 512, smem_in, sA>>>(x, in_b, ibn_g, ibn_b, ibn_m, ibn_v);
    cudaEventRecord(evA, sA);

    // stream B: CSR build
    k_zero2<<<(NN + 255) / 256, 256, 0, sB>>>(d_ideg, d_cursor, NN);
    k_hist<<<(EE + 255) / 256, 256, 0, sB>>>(dst);
    k_blocksum<<<SNB, SBS, 0, sB>>>();
    k_scanb<<<1, 256, 0, sB>>>();
    k_localscan<<<SNB, SBS, 0, sB>>>();
    k_fill<<<(EE + 255) / 256, 256, 0, sB>>>(src, dst);
    cudaEventRecord(evB, sB);

    // join on default stream
    cudaStreamWaitEvent(0, evA, 0);
    cudaStreamWaitEvent(0, evB, 0);

    for (int l = 0; l < LL; l++) {
        k_gather<<<(NN * 32 + 255) / 256, 256>>>();
        k_layer_mma<<<nsm, 512, smem_layer>>>(l, bl, bn_g, bn_b, bn_m, bn_v);
    }

    k_out_mma<<<nsm, 512, smem_out>>>(out_b, out);
}

// round 15
// speedup vs baseline: 1.0443x; 1.0443x over previous
#include <cuda_runtime.h>
#include <cuda_bf16.h>
#include <cstdint>

#define NN   100000
#define EE   600000
#define HH   128
#define CC   47
#define LL   3
#define EPSV 1e-5f

#define ASTR 136
#define BSTR 264
#define APLANE (128 * ASTR * 2)   // 34816 B
#define BPLANE (128 * BSTR * 2)   // 67584 B
#define OBPLANE (48 * ASTR * 2)   // 13056 B
#define NTILE ((NN + 127) / 128)  // 782

#define SBS  512
#define SNB  ((NN + SBS - 1) / SBS)   // 196

// Scratch (device globals; no allocation allowed)
__device__ float g_h[NN * HH];
__device__ float g_agg[NN * HH];
__device__ unsigned short g_wbhi_in[128 * ASTR];
__device__ unsigned short g_wblo_in[128 * ASTR];
__device__ unsigned short g_wbhi_l[LL * 128 * BSTR];
__device__ unsigned short g_wblo_l[LL * 128 * BSTR];
__device__ unsigned short g_wbhi_o[48 * ASTR];
__device__ unsigned short g_wblo_o[48 * ASTR];
__device__ int   g_ideg[NN];
__device__ int   g_rs[NN + 1];
__device__ int   g_bsum[SNB];
__device__ int   g_boff[SNB];
__device__ int   g_cursor[NN];
__device__ int   g_csrc[EE];

// ---------------------------------------------------------------------------
__device__ __forceinline__ uint32_t smem_u32(const void* p) {
    uint32_t a;
    asm("{ .reg .u64 t; cvta.to.shared.u64 t, %1; cvt.u32.u64 %0, t; }"
        : "=r"(a) : "l"(p));
    return a;
}
__device__ __forceinline__ void ldsm4(uint32_t* r, uint32_t addr) {
    asm volatile("ldmatrix.sync.aligned.m8n8.x4.shared.b16 {%0,%1,%2,%3}, [%4];"
                 : "=r"(r[0]), "=r"(r[1]), "=r"(r[2]), "=r"(r[3]) : "r"(addr));
}
__device__ __forceinline__ void mma16816(float* c, const uint32_t* a, const uint32_t* b) {
    asm volatile(
        "mma.sync.aligned.m16n8k16.row.col.f32.bf16.bf16.f32 "
        "{%0,%1,%2,%3}, {%4,%5,%6,%7}, {%8,%9}, {%0,%1,%2,%3};"
        : "+f"(c[0]), "+f"(c[1]), "+f"(c[2]), "+f"(c[3])
        : "r"(a[0]), "r"(a[1]), "r"(a[2]), "r"(a[3]), "r"(b[0]), "r"(b[1]));
}
__device__ __forceinline__ void split1(float x, unsigned short& hi, unsigned short& lo) {
    __nv_bfloat16 h = __float2bfloat16(x);
    float r = x - __bfloat162float(h);
    __nv_bfloat16 l = __float2bfloat16(r);
    hi = __bfloat16_as_ushort(h);
    lo = __bfloat16_as_ushort(l);
}
__device__ __forceinline__ float tof(unsigned short hi, unsigned short lo) {
    return __uint_as_float((uint32_t)hi << 16) + __uint_as_float((uint32_t)lo << 16);
}
__device__ __forceinline__ void cpa16(uint32_t dst, const void* src) {
    asm volatile("cp.async.cg.shared.global [%0], [%1], 16;" :: "r"(dst), "l"(src));
}
#define CP_COMMIT() asm volatile("cp.async.commit_group;" ::: "memory")
#define CP_WAIT0()  asm volatile("cp.async.wait_group 0;" ::: "memory")

// ---------------------------------------------------------------------------
// weight prep
__global__ void k_prep_in(const float* __restrict__ W) {
    int i = blockIdx.x * blockDim.x + threadIdx.x;
    if (i >= 128 * ASTR) return;
    int n = i / ASTR, k = i - n * ASTR;
    unsigned short hi = 0, lo = 0;
    if (k < 128) split1(W[k * 128 + n], hi, lo);
    g_wbhi_in[i] = hi;
    g_wblo_in[i] = lo;
}

__global__ void k_prep_layer(const float* __restrict__ Wl, const float* __restrict__ Wr) {
    int l = blockIdx.y;
    int i = blockIdx.x * blockDim.x + threadIdx.x;
    if (i >= 128 * BSTR) return;
    int n = i / BSTR, k = i - n * BSTR;
    unsigned short hi = 0, lo = 0;
    if (k < 128) split1(Wl[(long long)l * HH * HH + k * 128 + n], hi, lo);
    else if (k < 256) split1(Wr[(long long)l * HH * HH + (k - 128) * 128 + n], hi, lo);
    long long o = (long long)l * 128 * BSTR + i;
    g_wbhi_l[o] = hi;
    g_wblo_l[o] = lo;
}

__global__ void k_prep_out(const float* __restrict__ W) {
    int i = blockIdx.x * blockDim.x + threadIdx.x;
    if (i >= 48 * ASTR) return;
    int n = i / ASTR, k = i - n * ASTR;
    unsigned short hi = 0, lo = 0;
    if (k < 128 && n < CC) split1(W[k * CC + n], hi, lo);
    g_wbhi_o[i] = hi;
    g_wblo_o[i] = lo;
}

// ---------------------------------------------------------------------------
// CSR build
__global__ void k_zero2(int* __restrict__ a, int* __restrict__ b, int n) {
    int i = blockIdx.x * blockDim.x + threadIdx.x;
    if (i < n) { a[i] = 0; b[i] = 0; }
}

__global__ void k_hist(const int* __restrict__ dst) {
    int e = blockIdx.x * blockDim.x + threadIdx.x;
    if (e < EE) atomicAdd(&g_ideg[dst[e]], 1);
}

__global__ void __launch_bounds__(SBS) k_blocksum() {
    __shared__ int s[SBS];
    int i = blockIdx.x * SBS + threadIdx.x;
    s[threadIdx.x] = (i < NN) ? g_ideg[i] : 0;
    __syncthreads();
    for (int off = SBS / 2; off > 0; off >>= 1) {
        if (threadIdx.x < off) s[threadIdx.x] += s[threadIdx.x + off];
        __syncthreads();
    }
    if (threadIdx.x == 0) g_bsum[blockIdx.x] = s[0];
}

__global__ void __launch_bounds__(256) k_scanb() {
    __shared__ int s[SNB];
    int t = threadIdx.x;
    if (t < SNB) s[t] = g_bsum[t];
    __syncthreads();
    if (t == 0) {
        int acc = 0;
        for (int b = 0; b < SNB; b++) { int v = s[b]; s[b] = acc; acc += v; }
        g_rs[NN] = EE;
    }
    __syncthreads();
    if (t < SNB) g_boff[t] = s[t];
}

__global__ void __launch_bounds__(SBS) k_localscan() {
    __shared__ int s[SBS];
    int i = blockIdx.x * SBS + threadIdx.x;
    int d = (i < NN) ? g_ideg[i] : 0;
    s[threadIdx.x] = d;
    __syncthreads();
    for (int off = 1; off < SBS; off <<= 1) {
        int t = (threadIdx.x >= off) ? s[threadIdx.x - off] : 0;
        __syncthreads();
        s[threadIdx.x] += t;
        __syncthreads();
    }
    if (i < NN) g_rs[i] = g_boff[blockIdx.x] + s[threadIdx.x] - d;
}

__global__ void k_fill(const int* __restrict__ src, const int* __restrict__ dst) {
    int e = blockIdx.x * blockDim.x + threadIdx.x;
    if (e >= EE) return;
    int d = dst[e];
    int pos = g_rs[d] + atomicAdd(&g_cursor[d], 1);
    g_csrc[pos] = src[e];
}

// ---------------------------------------------------------------------------
// gather mean: agg[n] = mean of h[src] over in-edges (one warp per node, 4-wide)
__global__ void __launch_bounds__(256) k_gather() {
    int w = (blockIdx.x * blockDim.x + threadIdx.x) >> 5;
    int lane = threadIdx.x & 31;
    if (w >= NN) return;
    int beg = g_rs[w], end = g_rs[w + 1];
    const float4* h4 = (const float4*)g_h;
    float4 acc = make_float4(0.f, 0.f, 0.f, 0.f);
    int j = beg;
    for (; j + 3 < end; j += 4) {
        int s0 = g_csrc[j], s1 = g_csrc[j + 1], s2 = g_csrc[j + 2], s3 = g_csrc[j + 3];
        float4 v0 = __ldg(&h4[(long long)s0 * 32 + lane]);
        float4 v1 = __ldg(&h4[(long long)s1 * 32 + lane]);
        float4 v2 = __ldg(&h4[(long long)s2 * 32 + lane]);
        float4 v3 = __ldg(&h4[(long long)s3 * 32 + lane]);
        acc.x += (v0.x + v1.x) + (v2.x + v3.x);
        acc.y += (v0.y + v1.y) + (v2.y + v3.y);
        acc.z += (v0.z + v1.z) + (v2.z + v3.z);
        acc.w += (v0.w + v1.w) + (v2.w + v3.w);
    }
    for (; j < end; j++) {
        int s0 = g_csrc[j];
        float4 v0 = __ldg(&h4[(long long)s0 * 32 + lane]);
        acc.x += v0.x; acc.y += v0.y; acc.z += v0.z; acc.w += v0.w;
    }
    float inv = 1.0f / (float)max(end - beg, 1);
    acc.x *= inv; acc.y *= inv; acc.z *= inv; acc.w *= inv;
    ((float4*)g_agg)[(long long)w * 32 + lane] = acc;
}

// ---------------------------------------------------------------------------
// helpers: MLP=8 tile load + convert to split planes
__device__ __forceinline__ void load_tile8(float4* v, const float4* srcp, int row0, int tid) {
#pragma unroll
    for (int u = 0; u < 8; u++) {
        int i = tid + u * 512;
        int r = i >> 5, c4 = i & 31;
        int gr = row0 + r;
        v[u] = (gr < NN) ? __ldg(&srcp[(long long)gr * 32 + c4])
                         : make_float4(0.f, 0.f, 0.f, 0.f);
    }
}
__device__ __forceinline__ void conv_tile8(const float4* v, unsigned short* Ahi,
                                           unsigned short* Alo, int tid) {
#pragma unroll
    for (int u = 0; u < 8; u++) {
        int i = tid + u * 512;
        int r = i >> 5, k = (i & 31) * 4;
        ushort4 UH, UL;
        split1(v[u].x, UH.x, UL.x); split1(v[u].y, UH.y, UL.y);
        split1(v[u].z, UH.z, UL.z); split1(v[u].w, UH.w, UL.w);
        *(ushort4*)&Ahi[r * ASTR + k] = UH;
        *(ushort4*)&Alo[r * ASTR + k] = UL;
    }
}

// MMA over one 128-k chunk, 4x4 warp tiling (warp tile 32x32) — R13 shape
#define MMA_CHUNK(cacc, sAhi, sAlo, sBhi, sBlo, bstr, kb)                        \
    _Pragma("unroll 1")                                                          \
    for (int k0 = 0; k0 < 128; k0 += 16) {                                       \
        uint32_t ah[2][4], al[2][4];                                             \
        _Pragma("unroll")                                                        \
        for (int mt = 0; mt < 2; mt++) {                                         \
            uint32_t off = (wm * 32 + mt * 16 + a_row) * (ASTR * 2) +            \
                           (k0 + a_koff) * 2;                                    \
            ldsm4(ah[mt], (sAhi) + off);                                         \
            ldsm4(al[mt], (sAlo) + off);                                         \
        }                                                                        \
        uint32_t bh[4][2], bl[4][2];                                             \
        _Pragma("unroll")                                                        \
        for (int g = 0; g < 2; g++) {                                            \
            uint32_t off = (wn * 32 + g * 16 + b_row) * ((bstr) * 2) +           \
                           ((kb) + k0 + b_koff) * 2;                             \
            uint32_t tt[4];                                                      \
            ldsm4(tt, (sBhi) + off);                                             \
            bh[2 * g][0] = tt[0]; bh[2 * g][1] = tt[1];                          \
            bh[2 * g + 1][0] = tt[2]; bh[2 * g + 1][1] = tt[3];                  \
            ldsm4(tt, (sBlo) + off);                                             \
            bl[2 * g][0] = tt[0]; bl[2 * g][1] = tt[1];                          \
            bl[2 * g + 1][0] = tt[2]; bl[2 * g + 1][1] = tt[3];                  \
        }                                                                        \
        _Pragma("unroll")                                                        \
        for (int mt = 0; mt < 2; mt++)                                           \
            _Pragma("unroll")                                                    \
            for (int nt = 0; nt < 4; nt++) {                                     \
                mma16816(cacc[mt][nt], ah[mt], bh[nt]);                          \
                mma16816(cacc[mt][nt], ah[mt], bl[nt]);                          \
                mma16816(cacc[mt][nt], al[mt], bh[nt]);                          \
            }                                                                    \
    }

// ---------------------------------------------------------------------------
// input GEMM (mma.sync bf16 3-term split), PERSISTENT: h = relu(bn(x@W+b))
extern "C" __global__ void __launch_bounds__(512)
k_in_mma(const float* __restrict__ x, const float* __restrict__ bias,
         const float* __restrict__ bng, const float* __restrict__ bnb,
         const float* __restrict__ bnm, const float* __restrict__ bnv) {
    extern __shared__ char sm[];
    float* scp = (float*)sm;
    float* shp = (float*)(sm + 512);
    const uint32_t OFF_AHI = 1024;
    const uint32_t OFF_ALO = OFF_AHI + APLANE;
    const uint32_t OFF_BHI = OFF_ALO + APLANE;
    const uint32_t OFF_BLO = OFF_BHI + APLANE;
    unsigned short* Ahi = (unsigned short*)(sm + OFF_AHI);
    unsigned short* Alo = (unsigned short*)(sm + OFF_ALO);
    int tid = threadIdx.x;
    int wid = tid >> 5, lane = tid & 31;
    uint32_t sbase = smem_u32(sm);

    {
        const char* bh = (const char*)g_wbhi_in;
        const char* bl = (const char*)g_wblo_in;
        for (int i = tid * 16; i < APLANE; i += 512 * 16) {
            cpa16(sbase + OFF_BHI + i, bh + i);
            cpa16(sbase + OFF_BLO + i, bl + i);
        }
        CP_COMMIT();
    }
    if (tid < 128) {
        int c = tid;
        float s = bng[c] * rsqrtf(bnv[c] + EPSV);
        scp[c] = s;
        shp[c] = bnb[c] - bnm[c] * s + bias[c] * s;
    }
    CP_WAIT0();
    __syncthreads();

    int wm = wid & 3, wn = wid >> 2;   // 4x4 warp grid, warp tile 32x32
    uint32_t sAhi = sbase + OFF_AHI, sAlo = sbase + OFF_ALO;
    uint32_t sBhi = sbase + OFF_BHI, sBlo = sbase + OFF_BLO;
    uint32_t a_row = (lane & 15);
    uint32_t a_koff = (lane >> 4) << 3;
    uint32_t b_row = ((lane >> 4) << 3) + (lane & 7);
    uint32_t b_koff = ((lane >> 3) & 1) << 3;
    const float4* x4 = (const float4*)x;
    float2* h2 = (float2*)g_h;
    int rq = lane >> 2, cp = (lane & 3) * 2;

    float4 v[8];
    if (blockIdx.x < NTILE) load_tile8(v, x4, blockIdx.x * 128, tid);

    for (int t = blockIdx.x; t < NTILE; t += gridDim.x) {
        int row0 = t * 128;
        conv_tile8(v, Ahi, Alo, tid);
        int tn = t + gridDim.x;
        if (tn < NTILE) load_tile8(v, x4, tn * 128, tid);  // prefetch next tile
        __syncthreads();

        float c[2][4][4];
#pragma unroll
        for (int mt = 0; mt < 2; mt++)
#pragma unroll
            for (int nt = 0; nt < 4; nt++)
#pragma unroll
                for (int q = 0; q < 4; q++) c[mt][nt][q] = 0.f;

        MMA_CHUNK(c, sAhi, sAlo, sBhi, sBlo, ASTR, 0)

#pragma unroll
        for (int mt = 0; mt < 2; mt++)
#pragma unroll
            for (int nt = 0; nt < 4; nt++) {
                int col = wn * 32 + nt * 8 + cp;
                float s0 = scp[col], s1 = scp[col + 1];
                float t0 = shp[col], t1 = shp[col + 1];
                int r0g = row0 + wm * 32 + mt * 16 + rq;
                if (r0g < NN) {
                    float2 o;
                    o.x = fmaxf(fmaf(c[mt][nt][0], s0, t0), 0.f);
                    o.y = fmaxf(fmaf(c[mt][nt][1], s1, t1), 0.f);
                    h2[(long long)r0g * 64 + (col >> 1)] = o;
                }
                int r1g = r0g + 8;
                if (r1g < NN) {
                    float2 o;
                    o.x = fmaxf(fmaf(c[mt][nt][2], s0, t0), 0.f);
                    o.y = fmaxf(fmaf(c[mt][nt][3], s1, t1), 0.f);
                    h2[(long long)r1g * 64 + (col >> 1)] = o;
                }
            }
        __syncthreads();
    }
}

// ---------------------------------------------------------------------------
// layer GEMM, PERSISTENT: t = relu(bn([agg|h] @ [Wl;Wr] + bl)); h += t
// when last!=0: also computes out = h_final @ out_W + out_b for its tiles
extern "C" __global__ void __launch_bounds__(512)
k_layer_mma(int l, int last, float* __restrict__ outp, const float* __restrict__ obias,
            const float* __restrict__ blv,
            const float* __restrict__ bng, const float* __restrict__ bnb,
            const float* __restrict__ bnm, const float* __restrict__ bnv) {
    extern __shared__ char sm[];
    float* scp = (float*)sm;
    float* shp = (float*)(sm + 512);
    const uint32_t OFF_AHI = 1024;
    const uint32_t OFF_ALO = OFF_AHI + APLANE;
    const uint32_t OFF_BHI = OFF_ALO + APLANE;
    const uint32_t OFF_BLO = OFF_BHI + BPLANE;
    const uint32_t OFF_OBHI = OFF_BLO + BPLANE;
    const uint32_t OFF_OBLO = OFF_OBHI + OBPLANE;
    unsigned short* Ahi = (unsigned short*)(sm + OFF_AHI);
    unsigned short* Alo = (unsigned short*)(sm + OFF_ALO);
    int tid = threadIdx.x;
    int wid = tid >> 5, lane = tid & 31;
    uint32_t sbase = smem_u32(sm);

    {
        const char* bh = (const char*)(g_wbhi_l + (long long)l * 128 * BSTR);
        const char* bl = (const char*)(g_wblo_l + (long long)l * 128 * BSTR);
        for (int i = tid * 16; i < BPLANE; i += 512 * 16) {
            cpa16(sbase + OFF_BHI + i, bh + i);
            cpa16(sbase + OFF_BLO + i, bl + i);
        }
        if (last) {
            const char* oh = (const char*)g_wbhi_o;
            const char* ol = (const char*)g_wblo_o;
            for (int i = tid * 16; i < OBPLANE; i += 512 * 16) {
                cpa16(sbase + OFF_OBHI + i, oh + i);
                cpa16(sbase + OFF_OBLO + i, ol + i);
            }
        }
        CP_COMMIT();
    }
    if (tid < 128) {
        int c = tid;
        float s = bng[l * HH + c] * rsqrtf(bnv[l * HH + c] + EPSV);
        scp[c] = s;
        shp[c] = bnb[l * HH + c] - bnm[l * HH + c] * s + blv[l * HH + c] * s;
    }
    CP_WAIT0();
    __syncthreads();

    int wm = wid & 3, wn = wid >> 2;
    uint32_t sAhi = sbase + OFF_AHI, sAlo = sbase + OFF_ALO;
    uint32_t sBhi = sbase + OFF_BHI, sBlo = sbase + OFF_BLO;
    uint32_t a_row = (lane & 15);
    uint32_t a_koff = (lane >> 4) << 3;
    uint32_t b_row = ((lane >> 4) << 3) + (lane & 7);
    uint32_t b_koff = ((lane >> 3) & 1) << 3;
    const float4* agg4 = (const float4*)g_agg;
    const float4* h4g = (const float4*)g_h;
    float2* h2 = (float2*)g_h;
    int rq = lane >> 2, cp = (lane & 3) * 2;

    float4 vA[8], vH[8];
    if (blockIdx.x < NTILE) load_tile8(vA, agg4, blockIdx.x * 128, tid);

    for (int t = blockIdx.x; t < NTILE; t += gridDim.x) {
        int row0 = t * 128;
        float c[2][4][4];
#pragma unroll
        for (int mt = 0; mt < 2; mt++)
#pragma unroll
            for (int nt = 0; nt < 4; nt++)
#pragma unroll
                for (int q = 0; q < 4; q++) c[mt][nt][q] = 0.f;

        // chunk0: A = agg (vA preloaded); prefetch h for chunk1
        conv_tile8(vA, Ahi, Alo, tid);
        load_tile8(vH, h4g, row0, tid);  // overlaps chunk0 MMA
        __syncthreads();
        MMA_CHUNK(c, sAhi, sAlo, sBhi, sBlo, BSTR, 0)
        __syncthreads();

        // chunk1: A = h (vH preloaded); prefetch next tile's agg
        conv_tile8(vH, Ahi, Alo, tid);
        int tn = t + gridDim.x;
        if (tn < NTILE) load_tile8(vA, agg4, tn * 128, tid);  // overlaps chunk1 MMA
        __syncthreads();
        MMA_CHUNK(c, sAhi, sAlo, sBhi, sBlo, BSTR, 128)

        // epilogue: residual h reconstructed from chunk1 smem planes
#pragma unroll
        for (int mt = 0; mt < 2; mt++)
#pragma unroll
            for (int nt = 0; nt < 4; nt++) {
                int col = wn * 32 + nt * 8 + cp;
                float s0 = scp[col], s1 = scp[col + 1];
                float t0 = shp[col], t1 = shp[col + 1];
                int r0 = wm * 32 + mt * 16 + rq;
                int r0g = row0 + r0;
                if (r0g < NN) {
                    float hx = tof(Ahi[r0 * ASTR + col], Alo[r0 * ASTR + col]);
                    float hy = tof(Ahi[r0 * ASTR + col + 1], Alo[r0 * ASTR + col + 1]);
                    float2 o;
                    o.x = hx + fmaxf(fmaf(c[mt][nt][0], s0, t0), 0.f);
                    o.y = hy + fmaxf(fmaf(c[mt][nt][1], s1, t1), 0.f);
                    h2[(long long)r0g * 64 + (col >> 1)] = o;
                }
                int r1 = r0 + 8;
                int r1g = row0 + r1;
                if (r1g < NN) {
                    float hx = tof(Ahi[r1 * ASTR + col], Alo[r1 * ASTR + col]);
                    float hy = tof(Ahi[r1 * ASTR + col + 1], Alo[r1 * ASTR + col + 1]);
                    float2 o;
                    o.x = hx + fmaxf(fmaf(c[mt][nt][2], s0, t0), 0.f);
                    o.y = hy + fmaxf(fmaf(c[mt][nt][3], s1, t1), 0.f);
                    h2[(long long)r1g * 64 + (col >> 1)] = o;
                }
            }

        if (last) {
            __syncthreads();  // all residual smem reads + global h writes done
            // rebuild A planes from final h (L2-hot)
            {
                float4 vo[8];
                load_tile8(vo, h4g, row0, tid);
                conv_tile8(vo, Ahi, Alo, tid);
            }
            __syncthreads();
            // out GEMM: 8 warps, warp = 16 rows x 48 cols
            if (wid < 8) {
                float co[6][4];
#pragma unroll
                for (int nt = 0; nt < 6; nt++)
#pragma unroll
                    for (int q = 0; q < 4; q++) co[nt][q] = 0.f;
                uint32_t sOBhi = sbase + OFF_OBHI, sOBlo = sbase + OFF_OBLO;
#pragma unroll 1
                for (int k0 = 0; k0 < 128; k0 += 16) {
                    uint32_t ah[4], al[4];
                    {
                        uint32_t off = (wid * 16 + a_row) * (ASTR * 2) + (k0 + a_koff) * 2;
                        ldsm4(ah, sAhi + off);
                        ldsm4(al, sAlo + off);
                    }
                    uint32_t bh[6][2], bl[6][2];
#pragma unroll
                    for (int g = 0; g < 3; g++) {
                        uint32_t off = (g * 16 + b_row) * (ASTR * 2) + (k0 + b_koff) * 2;
                        uint32_t tt[4];
                        ldsm4(tt, sOBhi + off);
                        bh[2 * g][0] = tt[0]; bh[2 * g][1] = tt[1];
                        bh[2 * g + 1][0] = tt[2]; bh[2 * g + 1][1] = tt[3];
                        ldsm4(tt, sOBlo + off);
                        bl[2 * g][0] = tt[0]; bl[2 * g][1] = tt[1];
                        bl[2 * g + 1][0] = tt[2]; bl[2 * g + 1][1] = tt[3];
                    }
#pragma unroll
                    for (int nt = 0; nt < 6; nt++) {
                        mma16816(co[nt], ah, bh[nt]);
                        mma16816(co[nt], ah, bl[nt]);
                        mma16816(co[nt], al, bh[nt]);
                    }
                }
#pragma unroll
                for (int nt = 0; nt < 6; nt++) {
                    int col = nt * 8 + cp;
                    float b0 = __ldg(&obias[col]);
                    float b1 = (col + 1 < CC) ? __ldg(&obias[col + 1]) : 0.f;
                    int r0g = row0 + wid * 16 + rq;
                    if (r0g < NN) {
                        outp[(long long)r0g * CC + col] = co[nt][0] + b0;
                        if (col + 1 < CC)
                            outp[(long long)r0g * CC + col + 1] = co[nt][1] + b1;
                    }
                    int r1g = r0g + 8;
                    if (r1g < NN) {
                        outp[(long long)r1g * CC + col] = co[nt][2] + b0;
                        if (col + 1 < CC)
                            outp[(long long)r1g * CC + col + 1] = co[nt][3] + b1;
                    }
                }
            }
        }
        __syncthreads();  // smem reads done before next tile's convert
    }
}

// ---------------------------------------------------------------------------
extern "C" void kernel_launch(void* const* d_in, const int* in_sizes, int n_in,
                              void* d_out, int out_size) {
    const float* x     = (const float*)d_in[0];
    const float* in_W  = (const float*)d_in[1];
    const float* in_b  = (const float*)d_in[2];
    const float* ibn_g = (const float*)d_in[3];
    const float* ibn_b = (const float*)d_in[4];
    const float* ibn_m = (const float*)d_in[5];
    const float* ibn_v = (const float*)d_in[6];
    const float* Wl    = (const float*)d_in[7];
    const float* bl    = (const float*)d_in[8];
    const float* Wr    = (const float*)d_in[9];
    const float* bn_g  = (const float*)d_in[10];
    const float* bn_b  = (const float*)d_in[11];
    const float* bn_m  = (const float*)d_in[12];
    const float* bn_v  = (const float*)d_in[13];
    const float* out_W = (const float*)d_in[14];
    const float* out_b = (const float*)d_in[15];
    const int*   ei    = (const int*)d_in[16];
    const int* src = ei;
    const int* dst = ei + EE;
    float* out = (float*)d_out;

    static bool attr_done = false;
    static int nsm = 148;
    static cudaStream_t sA = 0, sB = 0;
    static cudaEvent_t evFork = 0, evA = 0, evB = 0;
    size_t smem_in    = 1024 + 4ull * APLANE;                               // ~137 KB
    size_t smem_layer = 1024 + 2ull * APLANE + 2ull * BPLANE + 2ull * OBPLANE; // 231936 B
    if (!attr_done) {
        cudaFuncSetAttribute(k_in_mma, cudaFuncAttributeMaxDynamicSharedMemorySize, (int)smem_in);
        cudaFuncSetAttribute(k_layer_mma, cudaFuncAttributeMaxDynamicSharedMemorySize, (int)smem_layer);
        cudaDeviceGetAttribute(&nsm, cudaDevAttrMultiProcessorCount, 0);
        cudaStreamCreateWithFlags(&sA, cudaStreamNonBlocking);
        cudaStreamCreateWithFlags(&sB, cudaStreamNonBlocking);
        cudaEventCreateWithFlags(&evFork, cudaEventDisableTiming);
        cudaEventCreateWithFlags(&evA, cudaEventDisableTiming);
        cudaEventCreateWithFlags(&evB, cudaEventDisableTiming);
        attr_done = true;
    }

    int* d_ideg;   cudaGetSymbolAddress((void**)&d_ideg, g_ideg);
    int* d_cursor; cudaGetSymbolAddress((void**)&d_cursor, g_cursor);

    // fork: stream A = weight prep + input GEMM; stream B = CSR build
    cudaEventRecord(evFork, 0);
    cudaStreamWaitEvent(sA, evFork, 0);
    cudaStreamWaitEvent(sB, evFork, 0);

    // stream A
    k_prep_in<<<(128 * ASTR + 255) / 256, 256, 0, sA>>>(in_W);
    k_prep_layer<<<dim3((128 * BSTR + 255) / 256, LL), 256, 0, sA>>>(Wl, Wr);
    k_prep_out<<<(48 * ASTR + 255) / 256, 256, 0, sA>>>(out_W);
    k_in_mma<<<nsm, 512, smem_in, sA>>>(x, in_b, ibn_g, ibn_b, ibn_m, ibn_v);
    cudaEventRecord(evA, sA);

    // stream B: CSR build
    k_zero2<<<(NN + 255) / 256, 256, 0, sB>>>(d_ideg, d_cursor, NN);
    k_hist<<<(EE + 255) / 256, 256, 0, sB>>>(dst);
    k_blocksum<<<SNB, SBS, 0, sB>>>();
    k_scanb<<<1, 256, 0, sB>>>();
    k_localscan<<<SNB, SBS, 0, sB>>>();
    k_fill<<<(EE + 255) / 256, 256, 0, sB>>>(src, dst);
    cudaEventRecord(evB, sB);

    // join on default stream
    cudaStreamWaitEvent(0, evA, 0);
    cudaStreamWaitEvent(0, evB, 0);

    for (int l = 0; l < LL; l++) {
        k_gather<<<(NN * 32 + 255) / 256, 256>>>();
        k_layer_mma<<<nsm, 512, smem_layer>>>(l, (l == LL - 1) ? 1 : 0, out, out_b,
                                              bl, bn_g, bn_b, bn_m, bn_v);
    }
}